// round 15
// baseline (speedup 1.0000x reference)
#include <cuda_runtime.h>
#include <cuda_bf16.h>
#include <cuda_fp16.h>
#include <math.h>
#include <stdint.h>

// Problem dims (fixed by dataset)
#define BB 2
#define SS 2048
#define DD 768
#define HH 12
#define HD 64
#define DFF 3072
#define MM (BB * SS)   // 4096 tokens

// ---------------- scratch (no allocations allowed) ----------------
__device__ __align__(16) __half h_x [MM * DD];
__device__ __align__(16) __half h_wq[DD * DD];
__device__ __align__(16) __half h_wk[DD * DD];
__device__ __align__(16) __half h_wv[DD * DD];
__device__ __align__(16) __half h_wp[DD * DD];
__device__ __align__(16) __half h_w1[DFF * DD];
__device__ __align__(16) __half h_w2[DD * DFF];
__device__ __align__(16) __half h_q [MM * DD];
__device__ __align__(16) __half h_k [MM * DD];
__device__ __align__(16) __half h_v [MM * DD];
__device__ __align__(16) __half h_at[MM * DD];
__device__ __align__(16) __half h_x1[MM * DD];
__device__ __align__(16) __half h_ff[MM * DFF];
__device__ __align__(16) float  g_pa [MM * DD];   // proj partial (K half 0)
__device__ __align__(16) float  g_pb [MM * DD];   // proj partial (K half 1)
__device__ __align__(16) float  g_x1f[MM * DD];
__device__ __align__(16) float  g_fa [MM * DD];   // ffn2 partial 0
__device__ __align__(16) float  g_fb [MM * DD];   // ffn2 partial 1

// ---------------- helpers --------------------------------------------------
__device__ __forceinline__ uint32_t pkh2(float x, float y) {
    __half2 h = __floats2half2_rn(x, y);
    return *reinterpret_cast<uint32_t*>(&h);
}
__device__ __forceinline__ void mma_f16(float* c, const uint32_t* a, const uint32_t* b) {
    asm volatile(
        "mma.sync.aligned.m16n8k16.row.col.f32.f16.f16.f32 "
        "{%0,%1,%2,%3},{%4,%5,%6,%7},{%8,%9},{%0,%1,%2,%3};\n"
        : "+f"(c[0]), "+f"(c[1]), "+f"(c[2]), "+f"(c[3])
        : "r"(a[0]), "r"(a[1]), "r"(a[2]), "r"(a[3]), "r"(b[0]), "r"(b[1]));
}
__device__ __forceinline__ void ldsm4(uint32_t* r, uint32_t addr) {
    asm volatile("ldmatrix.sync.aligned.m8n8.x4.shared.b16 {%0,%1,%2,%3}, [%4];"
                 : "=r"(r[0]), "=r"(r[1]), "=r"(r[2]), "=r"(r[3]) : "r"(addr));
}
__device__ __forceinline__ void ldsm2(uint32_t* r, uint32_t addr) {
    asm volatile("ldmatrix.sync.aligned.m8n8.x2.shared.b16 {%0,%1}, [%2];"
                 : "=r"(r[0]), "=r"(r[1]) : "r"(addr));
}
__device__ __forceinline__ void ldsm2t(uint32_t* r, uint32_t addr) {
    asm volatile("ldmatrix.sync.aligned.m8n8.x2.trans.shared.b16 {%0,%1}, [%2];"
                 : "=r"(r[0]), "=r"(r[1]) : "r"(addr));
}
__device__ __forceinline__ void cpa16(uint32_t s, const void* g) {
    asm volatile("cp.async.cg.shared.global [%0], [%1], 16;\n" :: "r"(s), "l"(g) : "memory");
}
#define CP_COMMIT() asm volatile("cp.async.commit_group;\n" ::: "memory")
#define CP_WAIT(n)  asm volatile("cp.async.wait_group %0;\n" :: "n"(n) : "memory")

// ---------------- fused fp32 -> fp16 conversion (one launch) ----------------
struct CvtArgs {
    const float* src[7];
    __half*      dst[7];
    int          cum[8];
};
__global__ __launch_bounds__(256)
void f2h_multi(CvtArgs a)
{
    const int idx = blockIdx.x * 256 + threadIdx.x;
    if (idx >= a.cum[7]) return;
    int seg = 0;
    #pragma unroll
    for (int j = 1; j < 7; ++j) seg += (idx >= a.cum[j]) ? 1 : 0;
    const int i = idx - a.cum[seg];
    const float4 lo = reinterpret_cast<const float4*>(a.src[seg])[2 * i];
    const float4 hi = reinterpret_cast<const float4*>(a.src[seg])[2 * i + 1];
    reinterpret_cast<uint4*>(a.dst[seg])[i] =
        make_uint4(pkh2(lo.x, lo.y), pkh2(lo.z, lo.w), pkh2(hi.x, hi.y), pkh2(hi.z, hi.w));
}

// ---------------- FP16 GEMM: 64x128 tile, 256 threads, 3-stage cp.async -----
// C[M,N] = A[M,K(+ofs)] @ W[N,K(+ofs)]^T (+bias)(+gelu).
// 8 warps in 2x4 grid, warp tile 32x32 (2x m16 x 4x n8). 4 blocks/SM resident.
// KSPLIT: blockIdx.z picks K half (length K, row stride LDK), raw fp32 out,
//         no bias. Otherwise blockIdx.z selects (W,bias,C) triple.
#define GSTAGES 3
#define GT_SMEM (GSTAGES * 192 * 40 * 2)   // 46080 B
template<int GELU, int OUT16, int KSPLIT>
__global__ __launch_bounds__(256, 4)
void gemm_a16(int K, int LDK, int N, const __half* __restrict__ A,
              const __half* __restrict__ W0, const float* __restrict__ b0, void* __restrict__ C0,
              const __half* __restrict__ W1_, const float* __restrict__ b1, void* __restrict__ C1,
              const __half* __restrict__ W2_, const float* __restrict__ b2, void* __restrict__ C2)
{
    constexpr int LDH = 40;           // halves per smem row (80B stride)
    constexpr int SH  = 192 * LDH;    // halves per stage (A 64 rows + W 128 rows)
    extern __shared__ __align__(16) char smem_raw[];
    const uint32_t sm_base = (uint32_t)__cvta_generic_to_shared(smem_raw);

    const int z = blockIdx.z;
    const __half* W;
    const float*  bia;
    void*         C;
    if (KSPLIT) {
        W = W0; bia = b0;
        C = (z == 0) ? C0 : C1;
    } else {
        W   = (z == 0) ? W0 : (z == 1) ? W1_ : W2_;
        bia = (z == 0) ? b0 : (z == 1) ? b1  : b2;
        C   = (z == 0) ? C0 : (z == 1) ? C1  : C2;
    }
    const int kofs = KSPLIT ? z * K : 0;

    const int tid  = threadIdx.x;
    const int lane = tid & 31;
    const int wid  = tid >> 5;
    const int wm   = (wid >> 2) * 32;   // 0 or 32 within the 64-row tile
    const int wn   = (wid & 3) * 32;
    const int l4   = lane >> 2;
    const int lm   = lane & 3;

    const __half* Ag = A + (size_t)blockIdx.y * 64 * LDK + kofs;
    const __half* Wg = W + (size_t)blockIdx.x * 128 * LDK + kofs;

    // staging: A 64 rows x 4 granules (256), W 128 rows x 4 granules (512);
    // per thread: 1 A granule + 2 W granules
    const int rS = tid >> 2, kS = (tid & 3) * 8;   // rS 0..63

    // ldmatrix source mapping (warp tile rows)
    const int rA  = (lane & 7) + ((lane >> 3) & 1) * 8;
    const int kA  = (lane >> 4) * 8;
    const int lB  = lane & 15;
    const int rB  = lB & 7;
    const int kB  = (lB >> 3) * 8;
    const uint32_t aRowOfs = (uint32_t)((wm + rA) * LDH + kA);
    const uint32_t bRowOfs = (uint32_t)((wn + rB) * LDH + kB);

    float acc[2][4][4];
    #pragma unroll
    for (int i = 0; i < 2; ++i)
        #pragma unroll
        for (int j = 0; j < 4; ++j)
            #pragma unroll
            for (int r = 0; r < 4; ++r) acc[i][j][r] = 0.f;

    auto issue = [&](int st, int k0) {
        const uint32_t sb = sm_base + (uint32_t)(st * SH) * 2;
        cpa16(sb + (uint32_t)(rS * LDH + kS) * 2, Ag + (size_t)rS * LDK + k0 + kS);
        cpa16(sb + (uint32_t)((64 + rS) * LDH + kS) * 2,
              Wg + (size_t)rS * LDK + k0 + kS);
        cpa16(sb + (uint32_t)((128 + rS) * LDH + kS) * 2,
              Wg + (size_t)(64 + rS) * LDK + k0 + kS);
        CP_COMMIT();
    };
    auto compute = [&](int st) {
        const uint32_t abuf = sm_base + (uint32_t)(st * SH) * 2;
        const uint32_t bbuf = abuf + (uint32_t)(64 * LDH) * 2;
        #pragma unroll
        for (int ks = 0; ks < 2; ++ks) {
            uint32_t af[2][4], bfr[4][2];
            #pragma unroll
            for (int i = 0; i < 2; ++i)
                ldsm4(af[i], abuf + (aRowOfs + (uint32_t)(i * 16 * LDH + ks * 16)) * 2);
            #pragma unroll
            for (int j = 0; j < 4; ++j)
                ldsm2(bfr[j], bbuf + (bRowOfs + (uint32_t)(j * 8 * LDH + ks * 16)) * 2);
            #pragma unroll
            for (int i = 0; i < 2; ++i)
                #pragma unroll
                for (int j = 0; j < 4; ++j)
                    mma_f16(acc[i][j], af[i], bfr[j]);
        }
    };

    const int nk = K / 32;
    issue(0, 0);
    issue(1, 32);
    for (int i = 0; i < nk; ++i) {
        if (i + 1 < nk) { CP_WAIT(1); } else { CP_WAIT(0); }
        __syncthreads();
        const int nx = i + 2;
        if (nx < nk) issue(nx % 3, nx * 32);
        compute(i % 3);
    }

    #pragma unroll
    for (int i = 0; i < 2; ++i) {
        const int row = blockIdx.y * 64 + wm + i * 16 + l4;
        #pragma unroll
        for (int j = 0; j < 4; ++j) {
            const int col = blockIdx.x * 128 + wn + j * 8 + lm * 2;
            if (KSPLIT) {
                float* Cf = (float*)C;
                *reinterpret_cast<float2*>(Cf + (size_t)row * N + col) =
                    make_float2(acc[i][j][0], acc[i][j][1]);
                *reinterpret_cast<float2*>(Cf + (size_t)(row + 8) * N + col) =
                    make_float2(acc[i][j][2], acc[i][j][3]);
            } else {
                const float bv0 = bia[col], bv1 = bia[col + 1];
                float v0 = acc[i][j][0] + bv0;
                float v1 = acc[i][j][1] + bv1;
                float v2 = acc[i][j][2] + bv0;
                float v3 = acc[i][j][3] + bv1;
                if (GELU) {
                    v0 = 0.5f * v0 * (1.f + erff(v0 * 0.70710678118654752f));
                    v1 = 0.5f * v1 * (1.f + erff(v1 * 0.70710678118654752f));
                    v2 = 0.5f * v2 * (1.f + erff(v2 * 0.70710678118654752f));
                    v3 = 0.5f * v3 * (1.f + erff(v3 * 0.70710678118654752f));
                }
                if (OUT16) {
                    __half* Ch = (__half*)C;
                    *reinterpret_cast<uint32_t*>(Ch + (size_t)row * N + col)       = pkh2(v0, v1);
                    *reinterpret_cast<uint32_t*>(Ch + (size_t)(row + 8) * N + col) = pkh2(v2, v3);
                } else {
                    float* Cf = (float*)C;
                    *reinterpret_cast<float2*>(Cf + (size_t)row * N + col)       = make_float2(v0, v1);
                    *reinterpret_cast<float2*>(Cf + (size_t)(row + 8) * N + col) = make_float2(v2, v3);
                }
            }
        }
    }
}

// ---------------- Attention: FA2-style fp16 MMA, double-buffered K/V --------
#define AT_LDH 72   // halves per smem row (144B): ldmatrix phases conflict-free
__global__ __launch_bounds__(128)
void attn_f16(const __half* __restrict__ q,
              const __half* __restrict__ k,
              const __half* __restrict__ v,
              const float* __restrict__ mask,
              __half* __restrict__ out)
{
    __shared__ __half Ks[2][64][AT_LDH];
    __shared__ __half Vs[2][64][AT_LDH];
    __shared__ float  msk[2][64];

    const int b    = blockIdx.z;
    const int h    = blockIdx.y;
    const int q0   = blockIdx.x * 64;
    const int tid  = threadIdx.x;
    const int w    = tid >> 5;
    const int lane = tid & 31;
    const int g    = lane >> 2;
    const int tg   = lane & 3;
    const int lB   = lane & 15;
    const int rBk  = lB & 7;
    const int kBk  = (lB >> 3) * 8;

    const size_t boff = (size_t)b * SS;
    const int hofs = h * HD;
    const int rlo  = q0 + w * 16 + g;

    const uint32_t ks0 = (uint32_t)__cvta_generic_to_shared(&Ks[0][0][0]);
    const uint32_t vs0 = (uint32_t)__cvta_generic_to_shared(&Vs[0][0][0]);
    constexpr uint32_t BUFB = 64 * AT_LDH * 2;

    auto issue = [&](int t) {
        const int kt = t * 64;
        const uint32_t bo = (uint32_t)(t & 1) * BUFB;
        #pragma unroll
        for (int it = 0; it < 4; ++it) {
            const int c  = it * 128 + tid;
            const int r  = c >> 3, cc = (c & 7) * 8;
            const size_t gofs = (boff + kt + r) * DD + hofs + cc;
            cpa16(ks0 + bo + (uint32_t)(r * AT_LDH + cc) * 2, k + gofs);
            cpa16(vs0 + bo + (uint32_t)(r * AT_LDH + cc) * 2, v + gofs);
        }
        CP_COMMIT();
        if (tid < 64) msk[t & 1][tid] = -10000.f * (1.f - mask[boff + kt + tid]);
    };

    uint32_t qa[4][4];
    {
        const __half* qlo = q + (boff + rlo) * DD + hofs;
        const __half* qhi = qlo + 8 * DD;
        const __half2 s = __float2half2_rn(0.125f);
        #pragma unroll
        for (int ks = 0; ks < 4; ++ks) {
            const int c0 = ks * 16 + 2 * tg;
            __half2 t0 = __hmul2(*reinterpret_cast<const __half2*>(qlo + c0), s);
            __half2 t1 = __hmul2(*reinterpret_cast<const __half2*>(qhi + c0), s);
            __half2 t2 = __hmul2(*reinterpret_cast<const __half2*>(qlo + c0 + 8), s);
            __half2 t3 = __hmul2(*reinterpret_cast<const __half2*>(qhi + c0 + 8), s);
            qa[ks][0] = *reinterpret_cast<uint32_t*>(&t0);
            qa[ks][1] = *reinterpret_cast<uint32_t*>(&t1);
            qa[ks][2] = *reinterpret_cast<uint32_t*>(&t2);
            qa[ks][3] = *reinterpret_cast<uint32_t*>(&t3);
        }
    }

    float o[8][4];
    #pragma unroll
    for (int j = 0; j < 8; ++j)
        #pragma unroll
        for (int r = 0; r < 4; ++r) o[j][r] = 0.f;
    float mx_lo = -1e30f, mx_hi = -1e30f, l_lo = 0.f, l_hi = 0.f;

    constexpr int NT = SS / 64;
    issue(0);

    for (int t = 0; t < NT; ++t) {
        if (t + 1 < NT) {
            issue(t + 1);
            CP_WAIT(1);
        } else {
            CP_WAIT(0);
        }
        __syncthreads();

        const int buf = t & 1;
        const uint32_t ks_base = ks0 + (uint32_t)buf * BUFB;
        const uint32_t vs_base = vs0 + (uint32_t)buf * BUFB;

        float sc[8][4];
        #pragma unroll
        for (int j = 0; j < 8; ++j) {
            sc[j][0] = sc[j][1] = sc[j][2] = sc[j][3] = 0.f;
            #pragma unroll
            for (int ks = 0; ks < 4; ++ks) {
                uint32_t bb[2];
                ldsm2(bb, ks_base + (uint32_t)((j * 8 + rBk) * AT_LDH + kBk + ks * 16) * 2);
                mma_f16(sc[j], qa[ks], bb);
            }
        }

        float nm_lo = mx_lo, nm_hi = mx_hi;
        #pragma unroll
        for (int j = 0; j < 8; ++j) {
            const float m0 = msk[buf][j * 8 + 2 * tg], m1 = msk[buf][j * 8 + 2 * tg + 1];
            sc[j][0] += m0; sc[j][1] += m1; sc[j][2] += m0; sc[j][3] += m1;
            nm_lo = fmaxf(nm_lo, fmaxf(sc[j][0], sc[j][1]));
            nm_hi = fmaxf(nm_hi, fmaxf(sc[j][2], sc[j][3]));
        }
        nm_lo = fmaxf(nm_lo, __shfl_xor_sync(0xFFFFFFFFu, nm_lo, 1));
        nm_lo = fmaxf(nm_lo, __shfl_xor_sync(0xFFFFFFFFu, nm_lo, 2));
        nm_hi = fmaxf(nm_hi, __shfl_xor_sync(0xFFFFFFFFu, nm_hi, 1));
        nm_hi = fmaxf(nm_hi, __shfl_xor_sync(0xFFFFFFFFu, nm_hi, 2));
        const float cor_lo = __expf(mx_lo - nm_lo);
        const float cor_hi = __expf(mx_hi - nm_hi);
        mx_lo = nm_lo; mx_hi = nm_hi;

        uint32_t pa[4][4];
        float sl_lo = 0.f, sl_hi = 0.f;
        #pragma unroll
        for (int j = 0; j < 8; ++j) {
            const float p0 = __expf(sc[j][0] - mx_lo);
            const float p1 = __expf(sc[j][1] - mx_lo);
            const float p2 = __expf(sc[j][2] - mx_hi);
            const float p3 = __expf(sc[j][3] - mx_hi);
            sl_lo += p0 + p1; sl_hi += p2 + p3;
            const int ks = j >> 1;
            if ((j & 1) == 0) {
                pa[ks][0] = pkh2(p0, p1);
                pa[ks][1] = pkh2(p2, p3);
            } else {
                pa[ks][2] = pkh2(p0, p1);
                pa[ks][3] = pkh2(p2, p3);
            }
        }
        sl_lo += __shfl_xor_sync(0xFFFFFFFFu, sl_lo, 1);
        sl_lo += __shfl_xor_sync(0xFFFFFFFFu, sl_lo, 2);
        sl_hi += __shfl_xor_sync(0xFFFFFFFFu, sl_hi, 1);
        sl_hi += __shfl_xor_sync(0xFFFFFFFFu, sl_hi, 2);
        l_lo = l_lo * cor_lo + sl_lo;
        l_hi = l_hi * cor_hi + sl_hi;
        #pragma unroll
        for (int j = 0; j < 8; ++j) {
            o[j][0] *= cor_lo; o[j][1] *= cor_lo;
            o[j][2] *= cor_hi; o[j][3] *= cor_hi;
        }

        #pragma unroll
        for (int ks = 0; ks < 4; ++ks) {
            #pragma unroll
            for (int j = 0; j < 8; ++j) {
                uint32_t bv[2];
                ldsm2t(bv, vs_base + (uint32_t)((ks * 16 + lB) * AT_LDH + j * 8) * 2);
                mma_f16(o[j], pa[ks], bv);
            }
        }
        __syncthreads();
    }

    const float inv_lo = 1.f / l_lo;
    const float inv_hi = 1.f / l_hi;
    __half* olo = out + (boff + rlo) * DD + hofs;
    __half* ohi = olo + 8 * DD;
    #pragma unroll
    for (int j = 0; j < 8; ++j) {
        *reinterpret_cast<uint32_t*>(olo + j * 8 + 2 * tg) =
            pkh2(o[j][0] * inv_lo, o[j][1] * inv_lo);
        *reinterpret_cast<uint32_t*>(ohi + j * 8 + 2 * tg) =
            pkh2(o[j][2] * inv_hi, o[j][3] * inv_hi);
    }
}

// ---------------- Fused 2-partial residual + bias + LayerNorm ---------------
template<int OUT16>
__global__ __launch_bounds__(192)
void ln3_kernel(const float* __restrict__ a,
                const float* __restrict__ p0, const float* __restrict__ p1,
                const float* __restrict__ bias,
                const float* __restrict__ gamma, const float* __restrict__ beta,
                float* __restrict__ out, __half* __restrict__ out16)
{
    const size_t base = (size_t)blockIdx.x * DD;
    const int t = threadIdx.x, c = t * 4;

    float4 v  = *reinterpret_cast<const float4*>(a + base + c);
    const float4 q0 = *reinterpret_cast<const float4*>(p0 + base + c);
    const float4 q1 = *reinterpret_cast<const float4*>(p1 + base + c);
    const float4 bb = *reinterpret_cast<const float4*>(bias + c);
    v.x += q0.x + q1.x + bb.x;
    v.y += q0.y + q1.y + bb.y;
    v.z += q0.z + q1.z + bb.z;
    v.w += q0.w + q1.w + bb.w;

    float s  = v.x + v.y + v.z + v.w;
    float ss = v.x * v.x + v.y * v.y + v.z * v.z + v.w * v.w;
    #pragma unroll
    for (int o = 16; o > 0; o >>= 1) {
        s  += __shfl_xor_sync(0xFFFFFFFFu, s,  o);
        ss += __shfl_xor_sync(0xFFFFFFFFu, ss, o);
    }
    __shared__ float rs[6], rss[6], stats[2];
    const int wid = t >> 5, lid = t & 31;
    if (lid == 0) { rs[wid] = s; rss[wid] = ss; }
    __syncthreads();
    if (t == 0) {
        float S = 0.f, SSq = 0.f;
        #pragma unroll
        for (int i = 0; i < 6; ++i) { S += rs[i]; SSq += rss[i]; }
        const float mu  = S * (1.f / DD);
        const float var = SSq * (1.f / DD) - mu * mu;
        stats[0] = mu;
        stats[1] = rsqrtf(var + 1e-12f);
    }
    __syncthreads();
    const float mu = stats[0], rstd = stats[1];

    const float4 g  = *reinterpret_cast<const float4*>(gamma + c);
    const float4 be = *reinterpret_cast<const float4*>(beta + c);
    float4 o4;
    o4.x = g.x * (v.x - mu) * rstd + be.x;
    o4.y = g.y * (v.y - mu) * rstd + be.y;
    o4.z = g.z * (v.z - mu) * rstd + be.z;
    o4.w = g.w * (v.w - mu) * rstd + be.w;
    *reinterpret_cast<float4*>(out + base + c) = o4;
    if (OUT16) {
        *reinterpret_cast<uint2*>(out16 + base + c) =
            make_uint2(pkh2(o4.x, o4.y), pkh2(o4.z, o4.w));
    }
}

// ---------------- launcher -------------------------------------------------
extern "C" void kernel_launch(void* const* d_in, const int* in_sizes, int n_in,
                              void* d_out, int out_size)
{
    const float* x    = (const float*)d_in[0];
    const float* mask = (const float*)d_in[1];
    const float* Wq   = (const float*)d_in[2];
    const float* bq   = (const float*)d_in[3];
    const float* Wk   = (const float*)d_in[4];
    const float* bk   = (const float*)d_in[5];
    const float* Wv   = (const float*)d_in[6];
    const float* bv   = (const float*)d_in[7];
    const float* Wp   = (const float*)d_in[8];
    const float* bp   = (const float*)d_in[9];
    const float* g1   = (const float*)d_in[10];
    const float* be1  = (const float*)d_in[11];
    const float* W1   = (const float*)d_in[12];
    const float* bf1  = (const float*)d_in[13];
    const float* W2   = (const float*)d_in[14];
    const float* bf2  = (const float*)d_in[15];
    const float* g2   = (const float*)d_in[16];
    const float* be2  = (const float*)d_in[17];
    float* outp = (float*)d_out;

    __half *phx, *phwq, *phwk, *phwv, *phwp, *phw1, *phw2;
    __half *phq, *phk, *phv, *phat, *phx1, *phff;
    float *ppa, *ppb, *px1f, *pfa, *pfb;
    cudaGetSymbolAddress((void**)&phx,  h_x);
    cudaGetSymbolAddress((void**)&phwq, h_wq);
    cudaGetSymbolAddress((void**)&phwk, h_wk);
    cudaGetSymbolAddress((void**)&phwv, h_wv);
    cudaGetSymbolAddress((void**)&phwp, h_wp);
    cudaGetSymbolAddress((void**)&phw1, h_w1);
    cudaGetSymbolAddress((void**)&phw2, h_w2);
    cudaGetSymbolAddress((void**)&phq,  h_q);
    cudaGetSymbolAddress((void**)&phk,  h_k);
    cudaGetSymbolAddress((void**)&phv,  h_v);
    cudaGetSymbolAddress((void**)&phat, h_at);
    cudaGetSymbolAddress((void**)&phx1, h_x1);
    cudaGetSymbolAddress((void**)&phff, h_ff);
    cudaGetSymbolAddress((void**)&ppa,  g_pa);
    cudaGetSymbolAddress((void**)&ppb,  g_pb);
    cudaGetSymbolAddress((void**)&px1f, g_x1f);
    cudaGetSymbolAddress((void**)&pfa,  g_fa);
    cudaGetSymbolAddress((void**)&pfb,  g_fb);

    cudaFuncSetAttribute(gemm_a16<0, 1, 0>, cudaFuncAttributeMaxDynamicSharedMemorySize, GT_SMEM);
    cudaFuncSetAttribute(gemm_a16<1, 1, 0>, cudaFuncAttributeMaxDynamicSharedMemorySize, GT_SMEM);
    cudaFuncSetAttribute(gemm_a16<0, 0, 1>, cudaFuncAttributeMaxDynamicSharedMemorySize, GT_SMEM);

    // single fused fp32->fp16 conversion launch (inputs + weights)
    {
        CvtArgs ca;
        const float* srcs[7] = { x, Wq, Wk, Wv, Wp, W1, W2 };
        __half*      dsts[7] = { phx, phwq, phwk, phwv, phwp, phw1, phw2 };
        const int    ns[7]   = { MM * DD, DD * DD, DD * DD, DD * DD, DD * DD,
                                 DFF * DD, DD * DFF };
        int cum = 0;
        for (int i = 0; i < 7; ++i) {
            ca.src[i] = srcs[i];
            ca.dst[i] = dsts[i];
            ca.cum[i] = cum;
            cum += ns[i] / 8;
        }
        ca.cum[7] = cum;
        f2h_multi<<<(cum + 255) / 256, 256>>>(ca);
    }

    // QKV projections (z selects W/bias/out): 1152 blocks x 256 thr
    gemm_a16<0, 1, 0><<<dim3(DD / 128, MM / 64, 3), 256, GT_SMEM>>>(
        DD, DD, DD, phx, phwq, bq, phq, phwk, bk, phk, phwv, bv, phv);

    // Attention (fp16 in/out, double-buffered K/V)
    attn_f16<<<dim3(SS / 64, HH, BB), 128>>>(phq, phk, phv, mask, phat);

    // Output projection, K split in 2 (z): partials -> LN1 fuses +x +bias
    gemm_a16<0, 0, 1><<<dim3(DD / 128, MM / 64, 2), 256, GT_SMEM>>>(
        DD / 2, DD, DD, phat, phwp, bp, ppa, nullptr, nullptr, ppb,
        nullptr, nullptr, nullptr);
    ln3_kernel<1><<<MM, 192>>>(x, ppa, ppb, bp, g1, be1, px1f, phx1);

    // FFN1 (+GELU): 1536 blocks
    gemm_a16<1, 1, 0><<<dim3(DFF / 128, MM / 64, 1), 256, GT_SMEM>>>(
        DD, DD, DFF, phx1, phw1, bf1, phff, phw1, bf1, phff, phw1, bf1, phff);

    // FFN2, K split in 2 (z): partials -> LN2 fuses +x1 +bias
    gemm_a16<0, 0, 1><<<dim3(DD / 128, MM / 64, 2), 256, GT_SMEM>>>(
        DFF / 2, DFF, DD, phff, phw2, bf2, pfa, nullptr, nullptr, pfb,
        nullptr, nullptr, nullptr);
    ln3_kernel<0><<<MM, 192>>>(px1f, pfa, pfb, bf2, g2, be2, outp, nullptr);
}

// round 16
// speedup vs baseline: 1.0332x; 1.0332x over previous
#include <cuda_runtime.h>
#include <cuda_bf16.h>
#include <cuda_fp16.h>
#include <math.h>
#include <stdint.h>

// Problem dims (fixed by dataset)
#define BB 2
#define SS 2048
#define DD 768
#define HH 12
#define HD 64
#define DFF 3072
#define MM (BB * SS)   // 4096 tokens

// ---------------- scratch (no allocations allowed) ----------------
__device__ __align__(16) __half h_x [MM * DD];
__device__ __align__(16) __half h_wq[DD * DD];
__device__ __align__(16) __half h_wk[DD * DD];
__device__ __align__(16) __half h_wv[DD * DD];
__device__ __align__(16) __half h_wp[DD * DD];
__device__ __align__(16) __half h_w1[DFF * DD];
__device__ __align__(16) __half h_w2[DD * DFF];
__device__ __align__(16) __half h_q [MM * DD];
__device__ __align__(16) __half h_k [MM * DD];
__device__ __align__(16) __half h_v [MM * DD];
__device__ __align__(16) __half h_at[MM * DD];
__device__ __align__(16) __half h_x1[MM * DD];
__device__ __align__(16) __half h_ff[MM * DFF];
__device__ __align__(16) float  g_pa [MM * DD];   // proj partial (K half 0)
__device__ __align__(16) float  g_pb [MM * DD];   // proj partial (K half 1)
__device__ __align__(16) float  g_x1f[MM * DD];
__device__ __align__(16) float  g_fa [MM * DD];   // ffn2 partial 0
__device__ __align__(16) float  g_fb [MM * DD];   // ffn2 partial 1

// ---------------- helpers --------------------------------------------------
__device__ __forceinline__ uint32_t pkh2(float x, float y) {
    __half2 h = __floats2half2_rn(x, y);
    return *reinterpret_cast<uint32_t*>(&h);
}
__device__ __forceinline__ void mma_f16(float* c, const uint32_t* a, const uint32_t* b) {
    asm volatile(
        "mma.sync.aligned.m16n8k16.row.col.f32.f16.f16.f32 "
        "{%0,%1,%2,%3},{%4,%5,%6,%7},{%8,%9},{%0,%1,%2,%3};\n"
        : "+f"(c[0]), "+f"(c[1]), "+f"(c[2]), "+f"(c[3])
        : "r"(a[0]), "r"(a[1]), "r"(a[2]), "r"(a[3]), "r"(b[0]), "r"(b[1]));
}
__device__ __forceinline__ void ldsm4(uint32_t* r, uint32_t addr) {
    asm volatile("ldmatrix.sync.aligned.m8n8.x4.shared.b16 {%0,%1,%2,%3}, [%4];"
                 : "=r"(r[0]), "=r"(r[1]), "=r"(r[2]), "=r"(r[3]) : "r"(addr));
}
__device__ __forceinline__ void ldsm2(uint32_t* r, uint32_t addr) {
    asm volatile("ldmatrix.sync.aligned.m8n8.x2.shared.b16 {%0,%1}, [%2];"
                 : "=r"(r[0]), "=r"(r[1]) : "r"(addr));
}
__device__ __forceinline__ void ldsm2t(uint32_t* r, uint32_t addr) {
    asm volatile("ldmatrix.sync.aligned.m8n8.x2.trans.shared.b16 {%0,%1}, [%2];"
                 : "=r"(r[0]), "=r"(r[1]) : "r"(addr));
}
__device__ __forceinline__ void cpa16(uint32_t s, const void* g) {
    asm volatile("cp.async.cg.shared.global [%0], [%1], 16;\n" :: "r"(s), "l"(g) : "memory");
}
#define CP_COMMIT() asm volatile("cp.async.commit_group;\n" ::: "memory")
#define CP_WAIT(n)  asm volatile("cp.async.wait_group %0;\n" :: "n"(n) : "memory")

// ---------------- fused fp32 -> fp16 conversion (one launch) ----------------
struct CvtArgs {
    const float* src[7];
    __half*      dst[7];
    int          cum[8];
};
__global__ __launch_bounds__(256)
void f2h_multi(CvtArgs a)
{
    const int idx = blockIdx.x * 256 + threadIdx.x;
    if (idx >= a.cum[7]) return;
    int seg = 0;
    #pragma unroll
    for (int j = 1; j < 7; ++j) seg += (idx >= a.cum[j]) ? 1 : 0;
    const int i = idx - a.cum[seg];
    const float4 lo = reinterpret_cast<const float4*>(a.src[seg])[2 * i];
    const float4 hi = reinterpret_cast<const float4*>(a.src[seg])[2 * i + 1];
    reinterpret_cast<uint4*>(a.dst[seg])[i] =
        make_uint4(pkh2(lo.x, lo.y), pkh2(lo.z, lo.w), pkh2(hi.x, hi.y), pkh2(hi.z, hi.w));
}

// ---------------- FP16 GEMM: 128x128 tile, 512 threads, 5-stage cp.async ----
// C[M,N] = A[M,K(+ofs)] @ W[N,K(+ofs)]^T (+bias)(+gelu).
// 16 warps in 4x4 grid, warp tile 32x32 (2x m16 x 4x n8).
// KSPLIT: blockIdx.z picks K half (length K, row stride LDK), raw fp32 out,
//         no bias. Otherwise blockIdx.z selects (W,bias,C) triple.
#define GSTAGES 5
#define GT_SMEM (GSTAGES * 256 * 40 * 2)   // 102400 B
template<int GELU, int OUT16, int KSPLIT>
__global__ __launch_bounds__(512, 2)
void gemm_a16(int K, int LDK, int N, const __half* __restrict__ A,
              const __half* __restrict__ W0, const float* __restrict__ b0, void* __restrict__ C0,
              const __half* __restrict__ W1_, const float* __restrict__ b1, void* __restrict__ C1,
              const __half* __restrict__ W2_, const float* __restrict__ b2, void* __restrict__ C2)
{
    constexpr int LDH = 40;           // halves per smem row (80B stride)
    constexpr int SH  = 256 * LDH;    // halves per stage (A 128 rows + W 128 rows)
    extern __shared__ __align__(16) char smem_raw[];
    const uint32_t sm_base = (uint32_t)__cvta_generic_to_shared(smem_raw);

    const int z = blockIdx.z;
    const __half* W;
    const float*  bia;
    void*         C;
    if (KSPLIT) {
        W = W0; bia = b0;
        C = (z == 0) ? C0 : C1;
    } else {
        W   = (z == 0) ? W0 : (z == 1) ? W1_ : W2_;
        bia = (z == 0) ? b0 : (z == 1) ? b1  : b2;
        C   = (z == 0) ? C0 : (z == 1) ? C1  : C2;
    }
    const int kofs = KSPLIT ? z * K : 0;

    const int tid  = threadIdx.x;
    const int lane = tid & 31;
    const int wid  = tid >> 5;
    const int wm   = (wid >> 2) * 32;
    const int wn   = (wid & 3) * 32;
    const int l4   = lane >> 2;
    const int lm   = lane & 3;

    const __half* Ag = A + (size_t)blockIdx.y * 128 * LDK + kofs;
    const __half* Wg = W + (size_t)blockIdx.x * 128 * LDK + kofs;

    // staging: 512 granules (16B) each for A and W; 1 + 1 per thread
    const int rS = tid >> 2, kS = (tid & 3) * 8;

    // ldmatrix source mapping
    // A (x4): m0,m1 = rows 0-15 k0-7; m2,m3 = rows 0-15 k8-15
    const int rA  = (lane & 7) + ((lane >> 3) & 1) * 8;
    const int kA  = (lane >> 4) * 8;
    // B (x4, two adjacent n8 tiles): m0=(j,k0-7) m1=(j,k8-15) m2=(j+1,k0-7) m3=(j+1,k8-15)
    const int rB4 = ((lane >> 4) << 3) + (lane & 7);
    const int kB4 = ((lane >> 3) & 1) * 8;
    const uint32_t aRowOfs = (uint32_t)((wm + rA) * LDH + kA);
    const uint32_t bRowOfs = (uint32_t)((wn + rB4) * LDH + kB4);

    float acc[2][4][4];
    #pragma unroll
    for (int i = 0; i < 2; ++i)
        #pragma unroll
        for (int j = 0; j < 4; ++j)
            #pragma unroll
            for (int r = 0; r < 4; ++r) acc[i][j][r] = 0.f;

    auto issue = [&](int st, int k0) {
        const uint32_t sb = sm_base + (uint32_t)(st * SH) * 2;
        cpa16(sb + (uint32_t)(rS * LDH + kS) * 2,         Ag + (size_t)rS * LDK + k0 + kS);
        cpa16(sb + (uint32_t)((128 + rS) * LDH + kS) * 2, Wg + (size_t)rS * LDK + k0 + kS);
        CP_COMMIT();
    };
    auto compute = [&](int st) {
        const uint32_t abuf = sm_base + (uint32_t)(st * SH) * 2;
        const uint32_t bbuf = abuf + (uint32_t)(128 * LDH) * 2;
        #pragma unroll
        for (int ks = 0; ks < 2; ++ks) {
            uint32_t af[2][4], bfr[4][2];
            #pragma unroll
            for (int i = 0; i < 2; ++i)
                ldsm4(af[i], abuf + (aRowOfs + (uint32_t)(i * 16 * LDH + ks * 16)) * 2);
            #pragma unroll
            for (int jj = 0; jj < 2; ++jj)
                ldsm4(&bfr[jj * 2][0],
                      bbuf + (bRowOfs + (uint32_t)(jj * 16 * LDH + ks * 16)) * 2);
            #pragma unroll
            for (int i = 0; i < 2; ++i)
                #pragma unroll
                for (int j = 0; j < 4; ++j)
                    mma_f16(acc[i][j], af[i], bfr[j]);
        }
    };

    const int nk = K / 32;
    issue(0, 0);
    issue(1, 32);
    issue(2, 64);
    issue(3, 96);
    for (int i = 0; i < nk; ++i) {
        if (i + 3 < nk)      { CP_WAIT(3); }
        else if (i + 2 < nk) { CP_WAIT(2); }
        else if (i + 1 < nk) { CP_WAIT(1); }
        else                 { CP_WAIT(0); }
        __syncthreads();
        const int nx = i + 4;
        if (nx < nk) issue(nx % GSTAGES, nx * 32);
        compute(i % GSTAGES);
    }

    #pragma unroll
    for (int i = 0; i < 2; ++i) {
        const int row = blockIdx.y * 128 + wm + i * 16 + l4;
        #pragma unroll
        for (int j = 0; j < 4; ++j) {
            const int col = blockIdx.x * 128 + wn + j * 8 + lm * 2;
            if (KSPLIT) {
                float* Cf = (float*)C;
                *reinterpret_cast<float2*>(Cf + (size_t)row * N + col) =
                    make_float2(acc[i][j][0], acc[i][j][1]);
                *reinterpret_cast<float2*>(Cf + (size_t)(row + 8) * N + col) =
                    make_float2(acc[i][j][2], acc[i][j][3]);
            } else {
                const float bv0 = bia[col], bv1 = bia[col + 1];
                float v0 = acc[i][j][0] + bv0;
                float v1 = acc[i][j][1] + bv1;
                float v2 = acc[i][j][2] + bv0;
                float v3 = acc[i][j][3] + bv1;
                if (GELU) {
                    v0 = 0.5f * v0 * (1.f + erff(v0 * 0.70710678118654752f));
                    v1 = 0.5f * v1 * (1.f + erff(v1 * 0.70710678118654752f));
                    v2 = 0.5f * v2 * (1.f + erff(v2 * 0.70710678118654752f));
                    v3 = 0.5f * v3 * (1.f + erff(v3 * 0.70710678118654752f));
                }
                if (OUT16) {
                    __half* Ch = (__half*)C;
                    *reinterpret_cast<uint32_t*>(Ch + (size_t)row * N + col)       = pkh2(v0, v1);
                    *reinterpret_cast<uint32_t*>(Ch + (size_t)(row + 8) * N + col) = pkh2(v2, v3);
                } else {
                    float* Cf = (float*)C;
                    *reinterpret_cast<float2*>(Cf + (size_t)row * N + col)       = make_float2(v0, v1);
                    *reinterpret_cast<float2*>(Cf + (size_t)(row + 8) * N + col) = make_float2(v2, v3);
                }
            }
        }
    }
}

// ---------------- Attention: FA2-style fp16 MMA, double-buffered K/V --------
#define AT_LDH 72   // halves per smem row (144B): ldmatrix phases conflict-free
__global__ __launch_bounds__(128)
void attn_f16(const __half* __restrict__ q,
              const __half* __restrict__ k,
              const __half* __restrict__ v,
              const float* __restrict__ mask,
              __half* __restrict__ out)
{
    __shared__ __half Ks[2][64][AT_LDH];
    __shared__ __half Vs[2][64][AT_LDH];
    __shared__ float  msk[2][64];

    const int b    = blockIdx.z;
    const int h    = blockIdx.y;
    const int q0   = blockIdx.x * 64;
    const int tid  = threadIdx.x;
    const int w    = tid >> 5;
    const int lane = tid & 31;
    const int g    = lane >> 2;
    const int tg   = lane & 3;
    const int lB   = lane & 15;
    const int rBk  = lB & 7;
    const int kBk  = (lB >> 3) * 8;

    const size_t boff = (size_t)b * SS;
    const int hofs = h * HD;
    const int rlo  = q0 + w * 16 + g;

    const uint32_t ks0 = (uint32_t)__cvta_generic_to_shared(&Ks[0][0][0]);
    const uint32_t vs0 = (uint32_t)__cvta_generic_to_shared(&Vs[0][0][0]);
    constexpr uint32_t BUFB = 64 * AT_LDH * 2;

    auto issue = [&](int t) {
        const int kt = t * 64;
        const uint32_t bo = (uint32_t)(t & 1) * BUFB;
        #pragma unroll
        for (int it = 0; it < 4; ++it) {
            const int c  = it * 128 + tid;
            const int r  = c >> 3, cc = (c & 7) * 8;
            const size_t gofs = (boff + kt + r) * DD + hofs + cc;
            cpa16(ks0 + bo + (uint32_t)(r * AT_LDH + cc) * 2, k + gofs);
            cpa16(vs0 + bo + (uint32_t)(r * AT_LDH + cc) * 2, v + gofs);
        }
        CP_COMMIT();
        if (tid < 64) msk[t & 1][tid] = -10000.f * (1.f - mask[boff + kt + tid]);
    };

    uint32_t qa[4][4];
    {
        const __half* qlo = q + (boff + rlo) * DD + hofs;
        const __half* qhi = qlo + 8 * DD;
        const __half2 s = __float2half2_rn(0.125f);
        #pragma unroll
        for (int ks = 0; ks < 4; ++ks) {
            const int c0 = ks * 16 + 2 * tg;
            __half2 t0 = __hmul2(*reinterpret_cast<const __half2*>(qlo + c0), s);
            __half2 t1 = __hmul2(*reinterpret_cast<const __half2*>(qhi + c0), s);
            __half2 t2 = __hmul2(*reinterpret_cast<const __half2*>(qlo + c0 + 8), s);
            __half2 t3 = __hmul2(*reinterpret_cast<const __half2*>(qhi + c0 + 8), s);
            qa[ks][0] = *reinterpret_cast<uint32_t*>(&t0);
            qa[ks][1] = *reinterpret_cast<uint32_t*>(&t1);
            qa[ks][2] = *reinterpret_cast<uint32_t*>(&t2);
            qa[ks][3] = *reinterpret_cast<uint32_t*>(&t3);
        }
    }

    float o[8][4];
    #pragma unroll
    for (int j = 0; j < 8; ++j)
        #pragma unroll
        for (int r = 0; r < 4; ++r) o[j][r] = 0.f;
    float mx_lo = -1e30f, mx_hi = -1e30f, l_lo = 0.f, l_hi = 0.f;

    constexpr int NT = SS / 64;
    issue(0);

    for (int t = 0; t < NT; ++t) {
        if (t + 1 < NT) {
            issue(t + 1);
            CP_WAIT(1);
        } else {
            CP_WAIT(0);
        }
        __syncthreads();

        const int buf = t & 1;
        const uint32_t ks_base = ks0 + (uint32_t)buf * BUFB;
        const uint32_t vs_base = vs0 + (uint32_t)buf * BUFB;

        float sc[8][4];
        #pragma unroll
        for (int j = 0; j < 8; ++j) {
            sc[j][0] = sc[j][1] = sc[j][2] = sc[j][3] = 0.f;
            #pragma unroll
            for (int ks = 0; ks < 4; ++ks) {
                uint32_t bb[2];
                ldsm2(bb, ks_base + (uint32_t)((j * 8 + rBk) * AT_LDH + kBk + ks * 16) * 2);
                mma_f16(sc[j], qa[ks], bb);
            }
        }

        float nm_lo = mx_lo, nm_hi = mx_hi;
        #pragma unroll
        for (int j = 0; j < 8; ++j) {
            const float m0 = msk[buf][j * 8 + 2 * tg], m1 = msk[buf][j * 8 + 2 * tg + 1];
            sc[j][0] += m0; sc[j][1] += m1; sc[j][2] += m0; sc[j][3] += m1;
            nm_lo = fmaxf(nm_lo, fmaxf(sc[j][0], sc[j][1]));
            nm_hi = fmaxf(nm_hi, fmaxf(sc[j][2], sc[j][3]));
        }
        nm_lo = fmaxf(nm_lo, __shfl_xor_sync(0xFFFFFFFFu, nm_lo, 1));
        nm_lo = fmaxf(nm_lo, __shfl_xor_sync(0xFFFFFFFFu, nm_lo, 2));
        nm_hi = fmaxf(nm_hi, __shfl_xor_sync(0xFFFFFFFFu, nm_hi, 1));
        nm_hi = fmaxf(nm_hi, __shfl_xor_sync(0xFFFFFFFFu, nm_hi, 2));
        const float cor_lo = __expf(mx_lo - nm_lo);
        const float cor_hi = __expf(mx_hi - nm_hi);
        mx_lo = nm_lo; mx_hi = nm_hi;

        uint32_t pa[4][4];
        float sl_lo = 0.f, sl_hi = 0.f;
        #pragma unroll
        for (int j = 0; j < 8; ++j) {
            const float p0 = __expf(sc[j][0] - mx_lo);
            const float p1 = __expf(sc[j][1] - mx_lo);
            const float p2 = __expf(sc[j][2] - mx_hi);
            const float p3 = __expf(sc[j][3] - mx_hi);
            sl_lo += p0 + p1; sl_hi += p2 + p3;
            const int ks = j >> 1;
            if ((j & 1) == 0) {
                pa[ks][0] = pkh2(p0, p1);
                pa[ks][1] = pkh2(p2, p3);
            } else {
                pa[ks][2] = pkh2(p0, p1);
                pa[ks][3] = pkh2(p2, p3);
            }
        }
        sl_lo += __shfl_xor_sync(0xFFFFFFFFu, sl_lo, 1);
        sl_lo += __shfl_xor_sync(0xFFFFFFFFu, sl_lo, 2);
        sl_hi += __shfl_xor_sync(0xFFFFFFFFu, sl_hi, 1);
        sl_hi += __shfl_xor_sync(0xFFFFFFFFu, sl_hi, 2);
        l_lo = l_lo * cor_lo + sl_lo;
        l_hi = l_hi * cor_hi + sl_hi;
        #pragma unroll
        for (int j = 0; j < 8; ++j) {
            o[j][0] *= cor_lo; o[j][1] *= cor_lo;
            o[j][2] *= cor_hi; o[j][3] *= cor_hi;
        }

        #pragma unroll
        for (int ks = 0; ks < 4; ++ks) {
            #pragma unroll
            for (int j = 0; j < 8; ++j) {
                uint32_t bv[2];
                ldsm2t(bv, vs_base + (uint32_t)((ks * 16 + lB) * AT_LDH + j * 8) * 2);
                mma_f16(o[j], pa[ks], bv);
            }
        }
        __syncthreads();
    }

    const float inv_lo = 1.f / l_lo;
    const float inv_hi = 1.f / l_hi;
    __half* olo = out + (boff + rlo) * DD + hofs;
    __half* ohi = olo + 8 * DD;
    #pragma unroll
    for (int j = 0; j < 8; ++j) {
        *reinterpret_cast<uint32_t*>(olo + j * 8 + 2 * tg) =
            pkh2(o[j][0] * inv_lo, o[j][1] * inv_lo);
        *reinterpret_cast<uint32_t*>(ohi + j * 8 + 2 * tg) =
            pkh2(o[j][2] * inv_hi, o[j][3] * inv_hi);
    }
}

// ---------------- Fused 2-partial residual + bias + LayerNorm ---------------
template<int OUT16>
__global__ __launch_bounds__(192)
void ln3_kernel(const float* __restrict__ a,
                const float* __restrict__ p0, const float* __restrict__ p1,
                const float* __restrict__ bias,
                const float* __restrict__ gamma, const float* __restrict__ beta,
                float* __restrict__ out, __half* __restrict__ out16)
{
    const size_t base = (size_t)blockIdx.x * DD;
    const int t = threadIdx.x, c = t * 4;

    float4 v  = *reinterpret_cast<const float4*>(a + base + c);
    const float4 q0 = *reinterpret_cast<const float4*>(p0 + base + c);
    const float4 q1 = *reinterpret_cast<const float4*>(p1 + base + c);
    const float4 bb = *reinterpret_cast<const float4*>(bias + c);
    v.x += q0.x + q1.x + bb.x;
    v.y += q0.y + q1.y + bb.y;
    v.z += q0.z + q1.z + bb.z;
    v.w += q0.w + q1.w + bb.w;

    float s  = v.x + v.y + v.z + v.w;
    float ss = v.x * v.x + v.y * v.y + v.z * v.z + v.w * v.w;
    #pragma unroll
    for (int o = 16; o > 0; o >>= 1) {
        s  += __shfl_xor_sync(0xFFFFFFFFu, s,  o);
        ss += __shfl_xor_sync(0xFFFFFFFFu, ss, o);
    }
    __shared__ float rs[6], rss[6], stats[2];
    const int wid = t >> 5, lid = t & 31;
    if (lid == 0) { rs[wid] = s; rss[wid] = ss; }
    __syncthreads();
    if (t == 0) {
        float S = 0.f, SSq = 0.f;
        #pragma unroll
        for (int i = 0; i < 6; ++i) { S += rs[i]; SSq += rss[i]; }
        const float mu  = S * (1.f / DD);
        const float var = SSq * (1.f / DD) - mu * mu;
        stats[0] = mu;
        stats[1] = rsqrtf(var + 1e-12f);
    }
    __syncthreads();
    const float mu = stats[0], rstd = stats[1];

    const float4 g  = *reinterpret_cast<const float4*>(gamma + c);
    const float4 be = *reinterpret_cast<const float4*>(beta + c);
    float4 o4;
    o4.x = g.x * (v.x - mu) * rstd + be.x;
    o4.y = g.y * (v.y - mu) * rstd + be.y;
    o4.z = g.z * (v.z - mu) * rstd + be.z;
    o4.w = g.w * (v.w - mu) * rstd + be.w;
    *reinterpret_cast<float4*>(out + base + c) = o4;
    if (OUT16) {
        *reinterpret_cast<uint2*>(out16 + base + c) =
            make_uint2(pkh2(o4.x, o4.y), pkh2(o4.z, o4.w));
    }
}

// ---------------- launcher -------------------------------------------------
extern "C" void kernel_launch(void* const* d_in, const int* in_sizes, int n_in,
                              void* d_out, int out_size)
{
    const float* x    = (const float*)d_in[0];
    const float* mask = (const float*)d_in[1];
    const float* Wq   = (const float*)d_in[2];
    const float* bq   = (const float*)d_in[3];
    const float* Wk   = (const float*)d_in[4];
    const float* bk   = (const float*)d_in[5];
    const float* Wv   = (const float*)d_in[6];
    const float* bv   = (const float*)d_in[7];
    const float* Wp   = (const float*)d_in[8];
    const float* bp   = (const float*)d_in[9];
    const float* g1   = (const float*)d_in[10];
    const float* be1  = (const float*)d_in[11];
    const float* W1   = (const float*)d_in[12];
    const float* bf1  = (const float*)d_in[13];
    const float* W2   = (const float*)d_in[14];
    const float* bf2  = (const float*)d_in[15];
    const float* g2   = (const float*)d_in[16];
    const float* be2  = (const float*)d_in[17];
    float* outp = (float*)d_out;

    __half *phx, *phwq, *phwk, *phwv, *phwp, *phw1, *phw2;
    __half *phq, *phk, *phv, *phat, *phx1, *phff;
    float *ppa, *ppb, *px1f, *pfa, *pfb;
    cudaGetSymbolAddress((void**)&phx,  h_x);
    cudaGetSymbolAddress((void**)&phwq, h_wq);
    cudaGetSymbolAddress((void**)&phwk, h_wk);
    cudaGetSymbolAddress((void**)&phwv, h_wv);
    cudaGetSymbolAddress((void**)&phwp, h_wp);
    cudaGetSymbolAddress((void**)&phw1, h_w1);
    cudaGetSymbolAddress((void**)&phw2, h_w2);
    cudaGetSymbolAddress((void**)&phq,  h_q);
    cudaGetSymbolAddress((void**)&phk,  h_k);
    cudaGetSymbolAddress((void**)&phv,  h_v);
    cudaGetSymbolAddress((void**)&phat, h_at);
    cudaGetSymbolAddress((void**)&phx1, h_x1);
    cudaGetSymbolAddress((void**)&phff, h_ff);
    cudaGetSymbolAddress((void**)&ppa,  g_pa);
    cudaGetSymbolAddress((void**)&ppb,  g_pb);
    cudaGetSymbolAddress((void**)&px1f, g_x1f);
    cudaGetSymbolAddress((void**)&pfa,  g_fa);
    cudaGetSymbolAddress((void**)&pfb,  g_fb);

    cudaFuncSetAttribute(gemm_a16<0, 1, 0>, cudaFuncAttributeMaxDynamicSharedMemorySize, GT_SMEM);
    cudaFuncSetAttribute(gemm_a16<1, 1, 0>, cudaFuncAttributeMaxDynamicSharedMemorySize, GT_SMEM);
    cudaFuncSetAttribute(gemm_a16<0, 0, 1>, cudaFuncAttributeMaxDynamicSharedMemorySize, GT_SMEM);

    // single fused fp32->fp16 conversion launch (inputs + weights)
    {
        CvtArgs ca;
        const float* srcs[7] = { x, Wq, Wk, Wv, Wp, W1, W2 };
        __half*      dsts[7] = { phx, phwq, phwk, phwv, phwp, phw1, phw2 };
        const int    ns[7]   = { MM * DD, DD * DD, DD * DD, DD * DD, DD * DD,
                                 DFF * DD, DD * DFF };
        int cum = 0;
        for (int i = 0; i < 7; ++i) {
            ca.src[i] = srcs[i];
            ca.dst[i] = dsts[i];
            ca.cum[i] = cum;
            cum += ns[i] / 8;
        }
        ca.cum[7] = cum;
        f2h_multi<<<(cum + 255) / 256, 256>>>(ca);
    }

    // QKV projections (z selects W/bias/out): 576 blocks x 512 thr
    gemm_a16<0, 1, 0><<<dim3(DD / 128, MM / 128, 3), 512, GT_SMEM>>>(
        DD, DD, DD, phx, phwq, bq, phq, phwk, bk, phk, phwv, bv, phv);

    // Attention (fp16 in/out, double-buffered K/V)
    attn_f16<<<dim3(SS / 64, HH, BB), 128>>>(phq, phk, phv, mask, phat);

    // Output projection, K split in 2 (z): partials -> LN1 fuses +x +bias
    gemm_a16<0, 0, 1><<<dim3(DD / 128, MM / 128, 2), 512, GT_SMEM>>>(
        DD / 2, DD, DD, phat, phwp, bp, ppa, nullptr, nullptr, ppb,
        nullptr, nullptr, nullptr);
    ln3_kernel<1><<<MM, 192>>>(x, ppa, ppb, bp, g1, be1, px1f, phx1);

    // FFN1 (+GELU)
    gemm_a16<1, 1, 0><<<dim3(DFF / 128, MM / 128, 1), 512, GT_SMEM>>>(
        DD, DD, DFF, phx1, phw1, bf1, phff, phw1, bf1, phff, phw1, bf1, phff);

    // FFN2, K split in 2 (z): partials -> LN2 fuses +x1 +bias
    gemm_a16<0, 0, 1><<<dim3(DD / 128, MM / 128, 2), 512, GT_SMEM>>>(
        DFF / 2, DFF, DD, phff, phw2, bf2, pfa, nullptr, nullptr, pfb,
        nullptr, nullptr, nullptr);
    ln3_kernel<0><<<MM, 192>>>(px1f, pfa, pfb, bf2, g2, be2, outp, nullptr);
}

// round 17
// speedup vs baseline: 1.0510x; 1.0172x over previous
#include <cuda_runtime.h>
#include <cuda_bf16.h>
#include <cuda_fp16.h>
#include <math.h>
#include <stdint.h>

// Problem dims (fixed by dataset)
#define BB 2
#define SS 2048
#define DD 768
#define HH 12
#define HD 64
#define DFF 3072
#define MM (BB * SS)   // 4096 tokens

// ---------------- scratch (no allocations allowed) ----------------
__device__ __align__(16) __half h_x [MM * DD];
__device__ __align__(16) __half h_wq[DD * DD];
__device__ __align__(16) __half h_wk[DD * DD];
__device__ __align__(16) __half h_wv[DD * DD];
__device__ __align__(16) __half h_wp[DD * DD];
__device__ __align__(16) __half h_w1[DFF * DD];
__device__ __align__(16) __half h_w2[DD * DFF];
__device__ __align__(16) __half h_q [MM * DD];
__device__ __align__(16) __half h_k [MM * DD];
__device__ __align__(16) __half h_v [MM * DD];
__device__ __align__(16) __half h_at[MM * DD];
__device__ __align__(16) __half h_x1[MM * DD];
__device__ __align__(16) __half h_ff[MM * DFF];
__device__ __align__(16) float  g_pa [MM * DD];   // proj partial (K third 0)
__device__ __align__(16) float  g_pb [MM * DD];   // proj partial (K third 1)
__device__ __align__(16) float  g_pc [MM * DD];   // proj partial (K third 2)
__device__ __align__(16) float  g_x1f[MM * DD];
__device__ __align__(16) float  g_fa [MM * DD];   // ffn2 partial 0
__device__ __align__(16) float  g_fb [MM * DD];   // ffn2 partial 1
__device__ __align__(16) float  g_fc [MM * DD];   // ffn2 partial 2

// ---------------- helpers --------------------------------------------------
__device__ __forceinline__ uint32_t pkh2(float x, float y) {
    __half2 h = __floats2half2_rn(x, y);
    return *reinterpret_cast<uint32_t*>(&h);
}
__device__ __forceinline__ void mma_f16(float* c, const uint32_t* a, const uint32_t* b) {
    asm volatile(
        "mma.sync.aligned.m16n8k16.row.col.f32.f16.f16.f32 "
        "{%0,%1,%2,%3},{%4,%5,%6,%7},{%8,%9},{%0,%1,%2,%3};\n"
        : "+f"(c[0]), "+f"(c[1]), "+f"(c[2]), "+f"(c[3])
        : "r"(a[0]), "r"(a[1]), "r"(a[2]), "r"(a[3]), "r"(b[0]), "r"(b[1]));
}
__device__ __forceinline__ void ldsm4(uint32_t* r, uint32_t addr) {
    asm volatile("ldmatrix.sync.aligned.m8n8.x4.shared.b16 {%0,%1,%2,%3}, [%4];"
                 : "=r"(r[0]), "=r"(r[1]), "=r"(r[2]), "=r"(r[3]) : "r"(addr));
}
__device__ __forceinline__ void ldsm2(uint32_t* r, uint32_t addr) {
    asm volatile("ldmatrix.sync.aligned.m8n8.x2.shared.b16 {%0,%1}, [%2];"
                 : "=r"(r[0]), "=r"(r[1]) : "r"(addr));
}
__device__ __forceinline__ void ldsm2t(uint32_t* r, uint32_t addr) {
    asm volatile("ldmatrix.sync.aligned.m8n8.x2.trans.shared.b16 {%0,%1}, [%2];"
                 : "=r"(r[0]), "=r"(r[1]) : "r"(addr));
}
__device__ __forceinline__ void cpa16(uint32_t s, const void* g) {
    asm volatile("cp.async.cg.shared.global [%0], [%1], 16;\n" :: "r"(s), "l"(g) : "memory");
}
#define CP_COMMIT() asm volatile("cp.async.commit_group;\n" ::: "memory")
#define CP_WAIT(n)  asm volatile("cp.async.wait_group %0;\n" :: "n"(n) : "memory")

// ---------------- fused fp32 -> fp16 conversion (one launch) ----------------
struct CvtArgs {
    const float* src[7];
    __half*      dst[7];
    int          cum[8];
};
__global__ __launch_bounds__(256)
void f2h_multi(CvtArgs a)
{
    const int idx = blockIdx.x * 256 + threadIdx.x;
    if (idx >= a.cum[7]) return;
    int seg = 0;
    #pragma unroll
    for (int j = 1; j < 7; ++j) seg += (idx >= a.cum[j]) ? 1 : 0;
    const int i = idx - a.cum[seg];
    const float4 lo = reinterpret_cast<const float4*>(a.src[seg])[2 * i];
    const float4 hi = reinterpret_cast<const float4*>(a.src[seg])[2 * i + 1];
    reinterpret_cast<uint4*>(a.dst[seg])[i] =
        make_uint4(pkh2(lo.x, lo.y), pkh2(lo.z, lo.w), pkh2(hi.x, hi.y), pkh2(hi.z, hi.w));
}

// ---------------- FP16 GEMM: 128x128 tile, 512 threads, 4-stage cp.async ----
// C[M,N] = A[M,K(+ofs)] @ W[N,K(+ofs)]^T (+bias)(+gelu).  (R10 baseline config)
// 16 warps in 4x4 grid, warp tile 32x32 (2x m16 x 4x n8).
// KSPLIT: blockIdx.z picks K third (length K, row stride LDK), raw fp32 out,
//         no bias. Otherwise blockIdx.z selects (W,bias,C) triple.
#define GSTAGES 4
#define GT_SMEM (GSTAGES * 256 * 40 * 2)   // 81920 B
template<int GELU, int OUT16, int KSPLIT>
__global__ __launch_bounds__(512, 2)
void gemm_a16(int K, int LDK, int N, const __half* __restrict__ A,
              const __half* __restrict__ W0, const float* __restrict__ b0, void* __restrict__ C0,
              const __half* __restrict__ W1_, const float* __restrict__ b1, void* __restrict__ C1,
              const __half* __restrict__ W2_, const float* __restrict__ b2, void* __restrict__ C2)
{
    constexpr int LDH = 40;           // halves per smem row (80B stride)
    constexpr int SH  = 256 * LDH;    // halves per stage (A 128 rows + W 128 rows)
    extern __shared__ __align__(16) char smem_raw[];
    const uint32_t sm_base = (uint32_t)__cvta_generic_to_shared(smem_raw);

    const int z = blockIdx.z;
    const __half* W;
    const float*  bia;
    void* C = (z == 0) ? C0 : (z == 1) ? C1 : C2;
    if (KSPLIT) {
        W = W0; bia = b0;
    } else {
        W   = (z == 0) ? W0 : (z == 1) ? W1_ : W2_;
        bia = (z == 0) ? b0 : (z == 1) ? b1  : b2;
    }
    const int kofs = KSPLIT ? z * K : 0;

    const int tid  = threadIdx.x;
    const int lane = tid & 31;
    const int wid  = tid >> 5;
    const int wm   = (wid >> 2) * 32;
    const int wn   = (wid & 3) * 32;
    const int l4   = lane >> 2;
    const int lm   = lane & 3;

    const __half* Ag = A + (size_t)blockIdx.y * 128 * LDK + kofs;
    const __half* Wg = W + (size_t)blockIdx.x * 128 * LDK + kofs;

    // staging: 512 granules (16B) each for A and W; 1 + 1 per thread
    const int rS = tid >> 2, kS = (tid & 3) * 8;

    // ldmatrix source mapping (R10 baseline: ldsm4 A, ldsm2 B)
    const int rA  = (lane & 7) + ((lane >> 3) & 1) * 8;
    const int kA  = (lane >> 4) * 8;
    const int lB  = lane & 15;
    const int rB  = lB & 7;
    const int kB  = (lB >> 3) * 8;
    const uint32_t aRowOfs = (uint32_t)((wm + rA) * LDH + kA);
    const uint32_t bRowOfs = (uint32_t)((wn + rB) * LDH + kB);

    float acc[2][4][4];
    #pragma unroll
    for (int i = 0; i < 2; ++i)
        #pragma unroll
        for (int j = 0; j < 4; ++j)
            #pragma unroll
            for (int r = 0; r < 4; ++r) acc[i][j][r] = 0.f;

    auto issue = [&](int st, int k0) {
        const uint32_t sb = sm_base + (uint32_t)(st * SH) * 2;
        cpa16(sb + (uint32_t)(rS * LDH + kS) * 2,         Ag + (size_t)rS * LDK + k0 + kS);
        cpa16(sb + (uint32_t)((128 + rS) * LDH + kS) * 2, Wg + (size_t)rS * LDK + k0 + kS);
        CP_COMMIT();
    };
    auto compute = [&](int st) {
        const uint32_t abuf = sm_base + (uint32_t)(st * SH) * 2;
        const uint32_t bbuf = abuf + (uint32_t)(128 * LDH) * 2;
        #pragma unroll
        for (int ks = 0; ks < 2; ++ks) {
            uint32_t af[2][4], bfr[4][2];
            #pragma unroll
            for (int i = 0; i < 2; ++i)
                ldsm4(af[i], abuf + (aRowOfs + (uint32_t)(i * 16 * LDH + ks * 16)) * 2);
            #pragma unroll
            for (int j = 0; j < 4; ++j)
                ldsm2(bfr[j], bbuf + (bRowOfs + (uint32_t)(j * 8 * LDH + ks * 16)) * 2);
            #pragma unroll
            for (int i = 0; i < 2; ++i)
                #pragma unroll
                for (int j = 0; j < 4; ++j)
                    mma_f16(acc[i][j], af[i], bfr[j]);
        }
    };

    const int nk = K / 32;
    issue(0, 0);
    issue(1, 32);
    issue(2, 64);
    for (int i = 0; i < nk; ++i) {
        if (i + 2 < nk)      { CP_WAIT(2); }
        else if (i + 1 < nk) { CP_WAIT(1); }
        else                 { CP_WAIT(0); }
        __syncthreads();
        const int nx = i + 3;
        if (nx < nk) issue(nx & 3, nx * 32);
        compute(i & 3);
    }

    #pragma unroll
    for (int i = 0; i < 2; ++i) {
        const int row = blockIdx.y * 128 + wm + i * 16 + l4;
        #pragma unroll
        for (int j = 0; j < 4; ++j) {
            const int col = blockIdx.x * 128 + wn + j * 8 + lm * 2;
            if (KSPLIT) {
                float* Cf = (float*)C;
                *reinterpret_cast<float2*>(Cf + (size_t)row * N + col) =
                    make_float2(acc[i][j][0], acc[i][j][1]);
                *reinterpret_cast<float2*>(Cf + (size_t)(row + 8) * N + col) =
                    make_float2(acc[i][j][2], acc[i][j][3]);
            } else {
                const float bv0 = bia[col], bv1 = bia[col + 1];
                float v0 = acc[i][j][0] + bv0;
                float v1 = acc[i][j][1] + bv1;
                float v2 = acc[i][j][2] + bv0;
                float v3 = acc[i][j][3] + bv1;
                if (GELU) {
                    v0 = 0.5f * v0 * (1.f + erff(v0 * 0.70710678118654752f));
                    v1 = 0.5f * v1 * (1.f + erff(v1 * 0.70710678118654752f));
                    v2 = 0.5f * v2 * (1.f + erff(v2 * 0.70710678118654752f));
                    v3 = 0.5f * v3 * (1.f + erff(v3 * 0.70710678118654752f));
                }
                if (OUT16) {
                    __half* Ch = (__half*)C;
                    *reinterpret_cast<uint32_t*>(Ch + (size_t)row * N + col)       = pkh2(v0, v1);
                    *reinterpret_cast<uint32_t*>(Ch + (size_t)(row + 8) * N + col) = pkh2(v2, v3);
                } else {
                    float* Cf = (float*)C;
                    *reinterpret_cast<float2*>(Cf + (size_t)row * N + col)       = make_float2(v0, v1);
                    *reinterpret_cast<float2*>(Cf + (size_t)(row + 8) * N + col) = make_float2(v2, v3);
                }
            }
        }
    }
}

// ---------------- Attention: FA2-style fp16 MMA, Q-tile 128, 256 threads ----
// 8 warps, each owns 16 queries (identical per-warp fragment code as before);
// K/V staged once per 128 queries -> half the L2 traffic of the 64-q version.
#define AT_LDH 72   // halves per smem row (144B): ldmatrix phases conflict-free
__global__ __launch_bounds__(256)
void attn_f16(const __half* __restrict__ q,
              const __half* __restrict__ k,
              const __half* __restrict__ v,
              const float* __restrict__ mask,
              __half* __restrict__ out)
{
    __shared__ __half Ks[2][64][AT_LDH];
    __shared__ __half Vs[2][64][AT_LDH];
    __shared__ float  msk[2][64];

    const int b    = blockIdx.z;
    const int h    = blockIdx.y;
    const int q0   = blockIdx.x * 128;
    const int tid  = threadIdx.x;
    const int w    = tid >> 5;      // 0..7
    const int lane = tid & 31;
    const int g    = lane >> 2;
    const int tg   = lane & 3;
    const int lB   = lane & 15;
    const int rBk  = lB & 7;
    const int kBk  = (lB >> 3) * 8;

    const size_t boff = (size_t)b * SS;
    const int hofs = h * HD;
    const int rlo  = q0 + w * 16 + g;

    const uint32_t ks0 = (uint32_t)__cvta_generic_to_shared(&Ks[0][0][0]);
    const uint32_t vs0 = (uint32_t)__cvta_generic_to_shared(&Vs[0][0][0]);
    constexpr uint32_t BUFB = 64 * AT_LDH * 2;

    auto issue = [&](int t) {
        const int kt = t * 64;
        const uint32_t bo = (uint32_t)(t & 1) * BUFB;
        #pragma unroll
        for (int it = 0; it < 2; ++it) {
            const int c  = it * 256 + tid;      // 0..511 granules
            const int r  = c >> 3, cc = (c & 7) * 8;
            const size_t gofs = (boff + kt + r) * DD + hofs + cc;
            cpa16(ks0 + bo + (uint32_t)(r * AT_LDH + cc) * 2, k + gofs);
            cpa16(vs0 + bo + (uint32_t)(r * AT_LDH + cc) * 2, v + gofs);
        }
        CP_COMMIT();
        if (tid < 64) msk[t & 1][tid] = -10000.f * (1.f - mask[boff + kt + tid]);
    };

    uint32_t qa[4][4];
    {
        const __half* qlo = q + (boff + rlo) * DD + hofs;
        const __half* qhi = qlo + 8 * DD;
        const __half2 s = __float2half2_rn(0.125f);
        #pragma unroll
        for (int ks = 0; ks < 4; ++ks) {
            const int c0 = ks * 16 + 2 * tg;
            __half2 t0 = __hmul2(*reinterpret_cast<const __half2*>(qlo + c0), s);
            __half2 t1 = __hmul2(*reinterpret_cast<const __half2*>(qhi + c0), s);
            __half2 t2 = __hmul2(*reinterpret_cast<const __half2*>(qlo + c0 + 8), s);
            __half2 t3 = __hmul2(*reinterpret_cast<const __half2*>(qhi + c0 + 8), s);
            qa[ks][0] = *reinterpret_cast<uint32_t*>(&t0);
            qa[ks][1] = *reinterpret_cast<uint32_t*>(&t1);
            qa[ks][2] = *reinterpret_cast<uint32_t*>(&t2);
            qa[ks][3] = *reinterpret_cast<uint32_t*>(&t3);
        }
    }

    float o[8][4];
    #pragma unroll
    for (int j = 0; j < 8; ++j)
        #pragma unroll
        for (int r = 0; r < 4; ++r) o[j][r] = 0.f;
    float mx_lo = -1e30f, mx_hi = -1e30f, l_lo = 0.f, l_hi = 0.f;

    constexpr int NT = SS / 64;
    issue(0);

    for (int t = 0; t < NT; ++t) {
        if (t + 1 < NT) {
            issue(t + 1);
            CP_WAIT(1);
        } else {
            CP_WAIT(0);
        }
        __syncthreads();

        const int buf = t & 1;
        const uint32_t ks_base = ks0 + (uint32_t)buf * BUFB;
        const uint32_t vs_base = vs0 + (uint32_t)buf * BUFB;

        float sc[8][4];
        #pragma unroll
        for (int j = 0; j < 8; ++j) {
            sc[j][0] = sc[j][1] = sc[j][2] = sc[j][3] = 0.f;
            #pragma unroll
            for (int ks = 0; ks < 4; ++ks) {
                uint32_t bb[2];
                ldsm2(bb, ks_base + (uint32_t)((j * 8 + rBk) * AT_LDH + kBk + ks * 16) * 2);
                mma_f16(sc[j], qa[ks], bb);
            }
        }

        float nm_lo = mx_lo, nm_hi = mx_hi;
        #pragma unroll
        for (int j = 0; j < 8; ++j) {
            const float m0 = msk[buf][j * 8 + 2 * tg], m1 = msk[buf][j * 8 + 2 * tg + 1];
            sc[j][0] += m0; sc[j][1] += m1; sc[j][2] += m0; sc[j][3] += m1;
            nm_lo = fmaxf(nm_lo, fmaxf(sc[j][0], sc[j][1]));
            nm_hi = fmaxf(nm_hi, fmaxf(sc[j][2], sc[j][3]));
        }
        nm_lo = fmaxf(nm_lo, __shfl_xor_sync(0xFFFFFFFFu, nm_lo, 1));
        nm_lo = fmaxf(nm_lo, __shfl_xor_sync(0xFFFFFFFFu, nm_lo, 2));
        nm_hi = fmaxf(nm_hi, __shfl_xor_sync(0xFFFFFFFFu, nm_hi, 1));
        nm_hi = fmaxf(nm_hi, __shfl_xor_sync(0xFFFFFFFFu, nm_hi, 2));
        const float cor_lo = __expf(mx_lo - nm_lo);
        const float cor_hi = __expf(mx_hi - nm_hi);
        mx_lo = nm_lo; mx_hi = nm_hi;

        uint32_t pa[4][4];
        float sl_lo = 0.f, sl_hi = 0.f;
        #pragma unroll
        for (int j = 0; j < 8; ++j) {
            const float p0 = __expf(sc[j][0] - mx_lo);
            const float p1 = __expf(sc[j][1] - mx_lo);
            const float p2 = __expf(sc[j][2] - mx_hi);
            const float p3 = __expf(sc[j][3] - mx_hi);
            sl_lo += p0 + p1; sl_hi += p2 + p3;
            const int ks = j >> 1;
            if ((j & 1) == 0) {
                pa[ks][0] = pkh2(p0, p1);
                pa[ks][1] = pkh2(p2, p3);
            } else {
                pa[ks][2] = pkh2(p0, p1);
                pa[ks][3] = pkh2(p2, p3);
            }
        }
        sl_lo += __shfl_xor_sync(0xFFFFFFFFu, sl_lo, 1);
        sl_lo += __shfl_xor_sync(0xFFFFFFFFu, sl_lo, 2);
        sl_hi += __shfl_xor_sync(0xFFFFFFFFu, sl_hi, 1);
        sl_hi += __shfl_xor_sync(0xFFFFFFFFu, sl_hi, 2);
        l_lo = l_lo * cor_lo + sl_lo;
        l_hi = l_hi * cor_hi + sl_hi;
        #pragma unroll
        for (int j = 0; j < 8; ++j) {
            o[j][0] *= cor_lo; o[j][1] *= cor_lo;
            o[j][2] *= cor_hi; o[j][3] *= cor_hi;
        }

        #pragma unroll
        for (int ks = 0; ks < 4; ++ks) {
            #pragma unroll
            for (int j = 0; j < 8; ++j) {
                uint32_t bv[2];
                ldsm2t(bv, vs_base + (uint32_t)((ks * 16 + lB) * AT_LDH + j * 8) * 2);
                mma_f16(o[j], pa[ks], bv);
            }
        }
        __syncthreads();
    }

    const float inv_lo = 1.f / l_lo;
    const float inv_hi = 1.f / l_hi;
    __half* olo = out + (boff + rlo) * DD + hofs;
    __half* ohi = olo + 8 * DD;
    #pragma unroll
    for (int j = 0; j < 8; ++j) {
        *reinterpret_cast<uint32_t*>(olo + j * 8 + 2 * tg) =
            pkh2(o[j][0] * inv_lo, o[j][1] * inv_lo);
        *reinterpret_cast<uint32_t*>(ohi + j * 8 + 2 * tg) =
            pkh2(o[j][2] * inv_hi, o[j][3] * inv_hi);
    }
}

// ---------------- Fused 3-partial residual + bias + LayerNorm ---------------
template<int OUT16>
__global__ __launch_bounds__(192)
void ln3_kernel(const float* __restrict__ a,
                const float* __restrict__ p0, const float* __restrict__ p1,
                const float* __restrict__ p2,
                const float* __restrict__ bias,
                const float* __restrict__ gamma, const float* __restrict__ beta,
                float* __restrict__ out, __half* __restrict__ out16)
{
    const size_t base = (size_t)blockIdx.x * DD;
    const int t = threadIdx.x, c = t * 4;

    float4 v  = *reinterpret_cast<const float4*>(a + base + c);
    const float4 q0 = *reinterpret_cast<const float4*>(p0 + base + c);
    const float4 q1 = *reinterpret_cast<const float4*>(p1 + base + c);
    const float4 q2 = *reinterpret_cast<const float4*>(p2 + base + c);
    const float4 bb = *reinterpret_cast<const float4*>(bias + c);
    v.x += q0.x + q1.x + q2.x + bb.x;
    v.y += q0.y + q1.y + q2.y + bb.y;
    v.z += q0.z + q1.z + q2.z + bb.z;
    v.w += q0.w + q1.w + q2.w + bb.w;

    float s  = v.x + v.y + v.z + v.w;
    float ss = v.x * v.x + v.y * v.y + v.z * v.z + v.w * v.w;
    #pragma unroll
    for (int o = 16; o > 0; o >>= 1) {
        s  += __shfl_xor_sync(0xFFFFFFFFu, s,  o);
        ss += __shfl_xor_sync(0xFFFFFFFFu, ss, o);
    }
    __shared__ float rs[6], rss[6], stats[2];
    const int wid = t >> 5, lid = t & 31;
    if (lid == 0) { rs[wid] = s; rss[wid] = ss; }
    __syncthreads();
    if (t == 0) {
        float S = 0.f, SSq = 0.f;
        #pragma unroll
        for (int i = 0; i < 6; ++i) { S += rs[i]; SSq += rss[i]; }
        const float mu  = S * (1.f / DD);
        const float var = SSq * (1.f / DD) - mu * mu;
        stats[0] = mu;
        stats[1] = rsqrtf(var + 1e-12f);
    }
    __syncthreads();
    const float mu = stats[0], rstd = stats[1];

    const float4 g  = *reinterpret_cast<const float4*>(gamma + c);
    const float4 be = *reinterpret_cast<const float4*>(beta + c);
    float4 o4;
    o4.x = g.x * (v.x - mu) * rstd + be.x;
    o4.y = g.y * (v.y - mu) * rstd + be.y;
    o4.z = g.z * (v.z - mu) * rstd + be.z;
    o4.w = g.w * (v.w - mu) * rstd + be.w;
    *reinterpret_cast<float4*>(out + base + c) = o4;
    if (OUT16) {
        *reinterpret_cast<uint2*>(out16 + base + c) =
            make_uint2(pkh2(o4.x, o4.y), pkh2(o4.z, o4.w));
    }
}

// ---------------- launcher -------------------------------------------------
extern "C" void kernel_launch(void* const* d_in, const int* in_sizes, int n_in,
                              void* d_out, int out_size)
{
    const float* x    = (const float*)d_in[0];
    const float* mask = (const float*)d_in[1];
    const float* Wq   = (const float*)d_in[2];
    const float* bq   = (const float*)d_in[3];
    const float* Wk   = (const float*)d_in[4];
    const float* bk   = (const float*)d_in[5];
    const float* Wv   = (const float*)d_in[6];
    const float* bv   = (const float*)d_in[7];
    const float* Wp   = (const float*)d_in[8];
    const float* bp   = (const float*)d_in[9];
    const float* g1   = (const float*)d_in[10];
    const float* be1  = (const float*)d_in[11];
    const float* W1   = (const float*)d_in[12];
    const float* bf1  = (const float*)d_in[13];
    const float* W2   = (const float*)d_in[14];
    const float* bf2  = (const float*)d_in[15];
    const float* g2   = (const float*)d_in[16];
    const float* be2  = (const float*)d_in[17];
    float* outp = (float*)d_out;

    __half *phx, *phwq, *phwk, *phwv, *phwp, *phw1, *phw2;
    __half *phq, *phk, *phv, *phat, *phx1, *phff;
    float *ppa, *ppb, *ppc, *px1f, *pfa, *pfb, *pfc;
    cudaGetSymbolAddress((void**)&phx,  h_x);
    cudaGetSymbolAddress((void**)&phwq, h_wq);
    cudaGetSymbolAddress((void**)&phwk, h_wk);
    cudaGetSymbolAddress((void**)&phwv, h_wv);
    cudaGetSymbolAddress((void**)&phwp, h_wp);
    cudaGetSymbolAddress((void**)&phw1, h_w1);
    cudaGetSymbolAddress((void**)&phw2, h_w2);
    cudaGetSymbolAddress((void**)&phq,  h_q);
    cudaGetSymbolAddress((void**)&phk,  h_k);
    cudaGetSymbolAddress((void**)&phv,  h_v);
    cudaGetSymbolAddress((void**)&phat, h_at);
    cudaGetSymbolAddress((void**)&phx1, h_x1);
    cudaGetSymbolAddress((void**)&phff, h_ff);
    cudaGetSymbolAddress((void**)&ppa,  g_pa);
    cudaGetSymbolAddress((void**)&ppb,  g_pb);
    cudaGetSymbolAddress((void**)&ppc,  g_pc);
    cudaGetSymbolAddress((void**)&px1f, g_x1f);
    cudaGetSymbolAddress((void**)&pfa,  g_fa);
    cudaGetSymbolAddress((void**)&pfb,  g_fb);
    cudaGetSymbolAddress((void**)&pfc,  g_fc);

    cudaFuncSetAttribute(gemm_a16<0, 1, 0>, cudaFuncAttributeMaxDynamicSharedMemorySize, GT_SMEM);
    cudaFuncSetAttribute(gemm_a16<1, 1, 0>, cudaFuncAttributeMaxDynamicSharedMemorySize, GT_SMEM);
    cudaFuncSetAttribute(gemm_a16<0, 0, 1>, cudaFuncAttributeMaxDynamicSharedMemorySize, GT_SMEM);

    // single fused fp32->fp16 conversion launch (inputs + weights)
    {
        CvtArgs ca;
        const float* srcs[7] = { x, Wq, Wk, Wv, Wp, W1, W2 };
        __half*      dsts[7] = { phx, phwq, phwk, phwv, phwp, phw1, phw2 };
        const int    ns[7]   = { MM * DD, DD * DD, DD * DD, DD * DD, DD * DD,
                                 DFF * DD, DD * DFF };
        int cum = 0;
        for (int i = 0; i < 7; ++i) {
            ca.src[i] = srcs[i];
            ca.dst[i] = dsts[i];
            ca.cum[i] = cum;
            cum += ns[i] / 8;
        }
        ca.cum[7] = cum;
        f2h_multi<<<(cum + 255) / 256, 256>>>(ca);
    }

    // QKV projections (z selects W/bias/out): 576 blocks x 512 thr
    gemm_a16<0, 1, 0><<<dim3(DD / 128, MM / 128, 3), 512, GT_SMEM>>>(
        DD, DD, DD, phx, phwq, bq, phq, phwk, bk, phk, phwv, bv, phv);

    // Attention (fp16 in/out, Q-tile 128, double-buffered K/V): 384 blocks
    attn_f16<<<dim3(SS / 128, HH, BB), 256>>>(phq, phk, phv, mask, phat);

    // Output projection, K split in 3 (z): partials -> LN1 fuses +x +bias
    gemm_a16<0, 0, 1><<<dim3(DD / 128, MM / 128, 3), 512, GT_SMEM>>>(
        DD / 3, DD, DD, phat, phwp, bp, ppa, nullptr, nullptr, ppb,
        nullptr, nullptr, ppc);
    ln3_kernel<1><<<MM, 192>>>(x, ppa, ppb, ppc, bp, g1, be1, px1f, phx1);

    // FFN1 (+GELU)
    gemm_a16<1, 1, 0><<<dim3(DFF / 128, MM / 128, 1), 512, GT_SMEM>>>(
        DD, DD, DFF, phx1, phw1, bf1, phff, phw1, bf1, phff, phw1, bf1, phff);

    // FFN2, K split in 3 (z): partials -> LN2 fuses +x1 +bias
    gemm_a16<0, 0, 1><<<dim3(DD / 128, MM / 128, 3), 512, GT_SMEM>>>(
        DFF / 3, DFF, DD, phff, phw2, bf2, pfa, nullptr, nullptr, pfb,
        nullptr, nullptr, pfc);
    ln3_kernel<0><<<MM, 192>>>(px1f, pfa, pfb, pfc, bf2, g2, be2, outp, nullptr);
}